// round 3
// baseline (speedup 1.0000x reference)
#include <cuda_runtime.h>
#include <cstdint>

#define NB      2
#define SEQ     2048
#define DMODEL  1024
#define HEADS   16
#define HD      64
#define MTOT    (NB*SEQ)        // 4096
#define N_QKV   (3*DMODEL)      // 3072

// Scratch (static device globals -- no allocation anywhere)
__device__ float g_qb[NB*HEADS*SEQ*HD];   // [b,h,s,hd]
__device__ float g_kb[NB*HEADS*SEQ*HD];
__device__ float g_vb[NB*HEADS*SEQ*HD];
__device__ float g_ab[MTOT*DMODEL];       // attention out, [b,s,h,hd] == [m, d]

// ---------------- helpers ----------------
__device__ __forceinline__ unsigned f2tf(float x) {
    unsigned u; asm("cvt.rna.tf32.f32 %0, %1;" : "=r"(u) : "f"(x)); return u;
}
__device__ __forceinline__ float f2tff(float x) { return __uint_as_float(f2tf(x)); }

__device__ __forceinline__ void mma8(float c[4],
                                     unsigned a0, unsigned a1, unsigned a2, unsigned a3,
                                     unsigned b0, unsigned b1) {
    asm volatile(
        "mma.sync.aligned.m16n8k8.row.col.f32.tf32.tf32.f32 "
        "{%0,%1,%2,%3}, {%4,%5,%6,%7}, {%8,%9}, {%0,%1,%2,%3};\n"
        : "+f"(c[0]), "+f"(c[1]), "+f"(c[2]), "+f"(c[3])
        : "r"(a0), "r"(a1), "r"(a2), "r"(a3), "r"(b0), "r"(b1));
}

// ---------------- GEMM: C[M,N] = A[M,K] @ B[N,K]^T + bias ----------------
// MODE 0: scatter into q/k/v buffers.  MODE 1: A is g_ab, write C row-major.
template<int MODE>
__global__ __launch_bounds__(256)
void gemm_kernel(const float* __restrict__ Ain, const float* __restrict__ B,
                 const float* __restrict__ bias, float* __restrict__ C,
                 int M, int N, int K)
{
    __shared__ float As[128*36];
    __shared__ float Bs[128*36];

    const float* A = (MODE == 1) ? g_ab : Ain;

    const int tid  = threadIdx.x;
    const int wid  = tid >> 5, lane = tid & 31;
    const int g    = lane >> 2, t = lane & 3;
    const int wm   = (wid >> 2) * 64;   // 2 warps in m
    const int wn   = (wid & 3) * 32;    // 4 warps in n
    const int m0   = blockIdx.y * 128, n0 = blockIdx.x * 128;

    float acc[4][4][4];
#pragma unroll
    for (int i = 0; i < 4; i++)
#pragma unroll
        for (int j = 0; j < 4; j++)
#pragma unroll
            for (int c = 0; c < 4; c++) acc[i][j][c] = 0.f;

    for (int k0 = 0; k0 < K; k0 += 32) {
#pragma unroll
        for (int i = 0; i < 4; i++) {
            int lin = tid + i * 256;                 // float4 index
            int row = lin >> 3, c4 = (lin & 7) << 2; // 8 float4 per row
            float4 va = *reinterpret_cast<const float4*>(&A[(size_t)(m0 + row) * K + k0 + c4]);
            float4 ta; ta.x = f2tff(va.x); ta.y = f2tff(va.y); ta.z = f2tff(va.z); ta.w = f2tff(va.w);
            *reinterpret_cast<float4*>(&As[row * 36 + c4]) = ta;
            float4 vb = *reinterpret_cast<const float4*>(&B[(size_t)(n0 + row) * K + k0 + c4]);
            float4 tb; tb.x = f2tff(vb.x); tb.y = f2tff(vb.y); tb.z = f2tff(vb.z); tb.w = f2tff(vb.w);
            *reinterpret_cast<float4*>(&Bs[row * 36 + c4]) = tb;
        }
        __syncthreads();
#pragma unroll
        for (int kk = 0; kk < 4; kk++) {
            unsigned a[4][4], b[4][2];
#pragma unroll
            for (int mf = 0; mf < 4; mf++) {
                int rb = wm + mf * 16;
                a[mf][0] = __float_as_uint(As[(rb + g    ) * 36 + kk * 8 + t    ]);
                a[mf][1] = __float_as_uint(As[(rb + g + 8) * 36 + kk * 8 + t    ]);
                a[mf][2] = __float_as_uint(As[(rb + g    ) * 36 + kk * 8 + t + 4]);
                a[mf][3] = __float_as_uint(As[(rb + g + 8) * 36 + kk * 8 + t + 4]);
            }
#pragma unroll
            for (int nf = 0; nf < 4; nf++) {
                int nb = wn + nf * 8;
                b[nf][0] = __float_as_uint(Bs[(nb + g) * 36 + kk * 8 + t    ]);
                b[nf][1] = __float_as_uint(Bs[(nb + g) * 36 + kk * 8 + t + 4]);
            }
#pragma unroll
            for (int mf = 0; mf < 4; mf++)
#pragma unroll
                for (int nf = 0; nf < 4; nf++)
                    mma8(acc[mf][nf], a[mf][0], a[mf][1], a[mf][2], a[mf][3],
                         b[nf][0], b[nf][1]);
        }
        __syncthreads();
    }

#pragma unroll
    for (int mf = 0; mf < 4; mf++)
#pragma unroll
        for (int nf = 0; nf < 4; nf++)
#pragma unroll
            for (int c = 0; c < 4; c++) {
                int row = m0 + wm + mf * 16 + g + ((c >= 2) ? 8 : 0);
                int col = n0 + wn + nf * 8 + 2 * t + (c & 1);
                float v = acc[mf][nf][c] + bias[col];
                if (MODE == 0) {
                    int part = col >> 10, nn = col & 1023;
                    int hh = nn >> 6, e = nn & 63;
                    int bb = row >> 11, sq = row & 2047;
                    float* dst = (part == 0) ? g_qb : ((part == 1) ? g_kb : g_vb);
                    dst[(((size_t)(bb * HEADS + hh)) * SEQ + sq) * HD + e] = v;
                } else {
                    C[(size_t)row * N + col] = v;
                }
            }
}

// ---------------- Flash attention ----------------
// Block = 128 threads (4 warps), one 64-row q tile for one (b,h).
__global__ __launch_bounds__(128)
void fa_kernel(const int* __restrict__ maskp)
{
    __shared__ float KS[64 * 68];   // K tile, then reused as S/P tile
    __shared__ float Vs[64 * 68];
    __shared__ float m_sh[64], l_sh[64], sc_sh[64];

    const int tid = threadIdx.x, wid = tid >> 5, lane = tid & 31;
    const int g = lane >> 2, t = lane & 3;
    const int qi = blockIdx.x, bh = blockIdx.y;
    const int causal = (maskp[0] != 0);

    const float* qp = g_qb + ((size_t)bh * SEQ + qi * 64) * HD;
    const float* kp = g_kb + (size_t)bh * SEQ * HD;
    const float* vp = g_vb + (size_t)bh * SEQ * HD;

    const int wr = wid * 16;

    // Q fragments resident in registers (tf32)
    unsigned qf[8][4];
#pragma unroll
    for (int kk = 0; kk < 8; kk++) {
        qf[kk][0] = f2tf(qp[(wr + g    ) * HD + kk * 8 + t    ]);
        qf[kk][1] = f2tf(qp[(wr + g + 8) * HD + kk * 8 + t    ]);
        qf[kk][2] = f2tf(qp[(wr + g    ) * HD + kk * 8 + t + 4]);
        qf[kk][3] = f2tf(qp[(wr + g + 8) * HD + kk * 8 + t + 4]);
    }

    float of[8][4];
#pragma unroll
    for (int nf = 0; nf < 8; nf++)
#pragma unroll
        for (int c = 0; c < 4; c++) of[nf][c] = 0.f;

    if (tid < 64) { m_sh[tid] = -1e30f; l_sh[tid] = 0.f; }

    const int jend = causal ? (qi + 1) : (SEQ / 64);
    for (int j = 0; j < jend; j++) {
        // stage K, V tiles (tf32-rounded)
#pragma unroll
        for (int i = 0; i < 8; i++) {
            int lin = tid + i * 128;
            int row = lin >> 4, c4 = (lin & 15) << 2;
            float4 kv = *reinterpret_cast<const float4*>(&kp[((size_t)(j * 64 + row)) * HD + c4]);
            float4 tk; tk.x = f2tff(kv.x); tk.y = f2tff(kv.y); tk.z = f2tff(kv.z); tk.w = f2tff(kv.w);
            *reinterpret_cast<float4*>(&KS[row * 68 + c4]) = tk;
            float4 vv = *reinterpret_cast<const float4*>(&vp[((size_t)(j * 64 + row)) * HD + c4]);
            float4 tv; tv.x = f2tff(vv.x); tv.y = f2tff(vv.y); tv.z = f2tff(vv.z); tv.w = f2tff(vv.w);
            *reinterpret_cast<float4*>(&Vs[row * 68 + c4]) = tv;
        }
        __syncthreads();

        // S = Q K^T
        float sf[8][4];
#pragma unroll
        for (int nf = 0; nf < 8; nf++)
#pragma unroll
            for (int c = 0; c < 4; c++) sf[nf][c] = 0.f;
#pragma unroll
        for (int kk = 0; kk < 8; kk++) {
#pragma unroll
            for (int nf = 0; nf < 8; nf++) {
                unsigned b0 = __float_as_uint(KS[(nf * 8 + g) * 68 + kk * 8 + t    ]);
                unsigned b1 = __float_as_uint(KS[(nf * 8 + g) * 68 + kk * 8 + t + 4]);
                mma8(sf[nf], qf[kk][0], qf[kk][1], qf[kk][2], qf[kk][3], b0, b1);
            }
        }
        __syncthreads();   // everyone done reading K before S overwrites it

        // scaled + masked scores into KS
#pragma unroll
        for (int nf = 0; nf < 8; nf++)
#pragma unroll
            for (int c = 0; c < 4; c++) {
                int row = wr + g + ((c >= 2) ? 8 : 0);
                int col = nf * 8 + 2 * t + (c & 1);
                float v = sf[nf][c] * 0.125f;            // 1/sqrt(64)
                if (causal && j == qi && col > row) v = -1e30f;
                KS[row * 68 + col] = v;
            }
        __syncthreads();

        // online softmax (one row per thread, 64 rows)
        if (tid < 64) {
            int r = tid;
            float mo = m_sh[r], mx = mo;
#pragma unroll 16
            for (int c = 0; c < 64; c++) mx = fmaxf(mx, KS[r * 68 + c]);
            float sc = __expf(mo - mx);
            float sum = 0.f;
#pragma unroll 16
            for (int c = 0; c < 64; c++) {
                float p = __expf(KS[r * 68 + c] - mx);
                KS[r * 68 + c] = p;
                sum += p;
            }
            l_sh[r] = l_sh[r] * sc + sum;
            m_sh[r] = mx;
            sc_sh[r] = sc;
        }
        __syncthreads();

        // rescale O, then O += P V
        float s0 = sc_sh[wr + g], s1 = sc_sh[wr + g + 8];
#pragma unroll
        for (int nf = 0; nf < 8; nf++) {
            of[nf][0] *= s0; of[nf][1] *= s0; of[nf][2] *= s1; of[nf][3] *= s1;
        }
#pragma unroll
        for (int kk = 0; kk < 8; kk++) {
            unsigned a0 = f2tf(KS[(wr + g    ) * 68 + kk * 8 + t    ]);
            unsigned a1 = f2tf(KS[(wr + g + 8) * 68 + kk * 8 + t    ]);
            unsigned a2 = f2tf(KS[(wr + g    ) * 68 + kk * 8 + t + 4]);
            unsigned a3 = f2tf(KS[(wr + g + 8) * 68 + kk * 8 + t + 4]);
#pragma unroll
            for (int nf = 0; nf < 8; nf++) {
                unsigned b0 = __float_as_uint(Vs[(kk * 8 + t    ) * 68 + nf * 8 + g]);
                unsigned b1 = __float_as_uint(Vs[(kk * 8 + t + 4) * 68 + nf * 8 + g]);
                mma8(of[nf], a0, a1, a2, a3, b0, b1);
            }
        }
        __syncthreads();
    }

    // normalize and write: out layout [b, s, h, hd] == [m, d]
    float l0 = 1.f / l_sh[wr + g], l1 = 1.f / l_sh[wr + g + 8];
    int b = bh >> 4, h = bh & 15;
#pragma unroll
    for (int nf = 0; nf < 8; nf++)
#pragma unroll
        for (int c = 0; c < 4; c++) {
            int row = wr + g + ((c >= 2) ? 8 : 0);
            int col = nf * 8 + 2 * t + (c & 1);
            int sq = qi * 64 + row;
            g_ab[(((size_t)b * SEQ + sq) * HEADS + h) * HD + col] =
                of[nf][c] * ((c >= 2) ? l1 : l0);
        }
}

// ---------------- launch ----------------
extern "C" void kernel_launch(void* const* d_in, const int* in_sizes, int n_in,
                              void* d_out, int out_size)
{
    const float* x    = (const float*)d_in[0];
    const float* Wqkv = (const float*)d_in[1];
    const float* bqkv = (const float*)d_in[2];
    const float* Wd   = (const float*)d_in[3];
    const float* bd   = (const float*)d_in[4];
    const int*   mask = (const int*)d_in[5];
    float* out = (float*)d_out;

    gemm_kernel<0><<<dim3(N_QKV / 128, MTOT / 128), 256>>>(
        x, Wqkv, bqkv, nullptr, MTOT, N_QKV, DMODEL);

    fa_kernel<<<dim3(SEQ / 64, NB * HEADS), 128>>>(mask);

    gemm_kernel<1><<<dim3(DMODEL / 128, MTOT / 128), 256>>>(
        nullptr, Wd, bd, out, MTOT, DMODEL, DMODEL);
}